// round 14
// baseline (speedup 1.0000x reference)
#include <cuda_runtime.h>
#include <cuda_fp16.h>
#include <cstdint>

#define SEQ   4096
#define DIM   512
#define BATCH 4
#define MTOT  (BATCH*SEQ)

// Device-global scratch (allocation-free).
__device__ __align__(16) __half g_xh [(size_t)MTOT * DIM];
__device__ __align__(16) __half g_WT [3][(size_t)DIM * DIM];   // W^T fp16
__device__ __align__(16) __half g_Qh [(size_t)MTOT * DIM];
__device__ __align__(16) __half g_Kh [(size_t)MTOT * DIM];
__device__ __align__(16) __half g_Vh [(size_t)MTOT * DIM];
__device__ __align__(16) __half g_VTh[(size_t)BATCH * DIM * SEQ]; // V^T fp16
__device__ __align__(16) __half g_Ph [(size_t)BATCH * SEQ * SEQ]; // probs fp16
__device__ float g_L[(size_t)BATCH * SEQ];                        // denominators

struct Proj3Args {
    const __half* B[3];
    const float*  bias[3];
    __half*       C[3];
};

// ---------------------------------------------------------------------------
__device__ __forceinline__ void mma_f16(float* d, const unsigned* a,
                                        const unsigned* b) {
    asm volatile(
        "mma.sync.aligned.m16n8k16.row.col.f32.f16.f16.f32 "
        "{%0,%1,%2,%3}, {%4,%5,%6,%7}, {%8,%9}, {%0,%1,%2,%3};"
        : "+f"(d[0]), "+f"(d[1]), "+f"(d[2]), "+f"(d[3])
        : "r"(a[0]), "r"(a[1]), "r"(a[2]), "r"(a[3]),
          "r"(b[0]), "r"(b[1]));
}
__device__ __forceinline__ uint32_t smem_u32(const void* p) {
    uint32_t a;
    asm("{ .reg .u64 t; cvta.to.shared.u64 t, %1; cvt.u32.u64 %0, t; }"
        : "=r"(a) : "l"(p));
    return a;
}
__device__ __forceinline__ void cp16(uint32_t dst, const void* src) {
    asm volatile("cp.async.ca.shared.global [%0], [%1], 16;"
                 :: "r"(dst), "l"(src));
}
__device__ __forceinline__ void cp_commit() {
    asm volatile("cp.async.commit_group;");
}
__device__ __forceinline__ void cp_wait1() {
    asm volatile("cp.async.wait_group 1;");
}

// Per-MT stage geometry (halfs): [A: MT*40 | B: 128*40], 3 stages.
// Threads per CTA == MT (128 -> 4 warps 2x2; 64 -> 2 warps 1x2).
#define GEMM_SMEM_MT(MT) (3 * ((MT) * 40 + 128 * 40) * 2)

// ---------------------------------------------------------------------------
// fp16 NT GEMM:  C = A @ B^T.  A:[M,K] halfs k-major, B:[N,K] halfs k-major.
// CTA tile MT x 128, MT threads, k-slab 32, 3-stage cp.async pipeline.
// Warp tile 64x64 (4 m-tiles x 8 n-tiles of m16n8k16) in both MT configs.
// smem rows padded to 40 halfs (20 words): frag banks (g*20+t4)%32 distinct.
// Modes: PROJ3 (z selects W/bias/out; +bias, half out),
//        EXP (exp*sc + row-sum atomics, half out), DIV (/L, float out).
// ---------------------------------------------------------------------------
template<int MT, bool PROJ3, bool EXP_EPI, bool DIV_EPI, typename CT>
__global__ __launch_bounds__(MT, 384 / MT) void gemm_h(
    const __half* __restrict__ A, const __half* __restrict__ B,
    const float* __restrict__ bias, CT* __restrict__ C,
    float* __restrict__ Lsum,
    int M, int N, int K, long sA, long sB, long sC, Proj3Args p3)
{
    if (PROJ3) {
        B    = p3.B[blockIdx.z];
        bias = p3.bias[blockIdx.z];
        C    = (CT*)p3.C[blockIdx.z];
    } else {
        A += (long)blockIdx.z * sA;
        B += (long)blockIdx.z * sB;
        C += (long)blockIdx.z * sC;
        if (EXP_EPI || DIV_EPI) Lsum += (long)blockIdx.z * SEQ;
    }

    constexpr int WM     = MT / 64;          // warp-grid m extent (1 or 2)
    constexpr int ATILEH = MT * 40;          // A halfs per stage
    constexpr int BTILEH = 128 * 40;         // B halfs per stage
    constexpr int STAGEH = ATILEH + BTILEH;
    constexpr int BITERS = 512 / MT;         // B 16B-chunks per thread

    extern __shared__ __align__(16) __half smh[];

    const int tid  = threadIdx.x;
    const int lane = tid & 31, w = tid >> 5;
    const int g    = lane >> 2, t4 = lane & 3;
    const int wm   = w % WM, wn = w / WM;
    const int m0   = blockIdx.y * MT, n0 = blockIdx.x * 128;

    const uint32_t sb = smem_u32(smh);

    auto issue_stage = [&](int s, int st) {
        const int k0 = s << 5;
        const uint32_t ab = sb + st * (STAGEH * 2);
        #pragma unroll
        for (int i = 0; i < 4; i++) {       // A: MT*4 chunks, 4/thread
            int c = tid + i * MT;
            int row = c >> 2, ko = (c & 3) * 8;
            cp16(ab + row * 80 + ko * 2,
                 &A[(long)(m0 + row) * K + k0 + ko]);
        }
        const uint32_t bb = ab + ATILEH * 2;
        #pragma unroll
        for (int i = 0; i < BITERS; i++) {  // B: 512 chunks
            int c = tid + i * MT;
            int row = c >> 2, ko = (c & 3) * 8;
            cp16(bb + row * 80 + ko * 2,
                 &B[(long)(n0 + row) * K + k0 + ko]);
        }
    };

    float acc[4][8][4];
    #pragma unroll
    for (int mt = 0; mt < 4; mt++)
        #pragma unroll
        for (int nt = 0; nt < 8; nt++)
            #pragma unroll
            for (int i = 0; i < 4; i++) acc[mt][nt][i] = 0.f;

    const int nslab = K >> 5;
    issue_stage(0, 0); cp_commit();
    issue_stage(1, 1); cp_commit();

    for (int s = 0; s < nslab; s++) {
        cp_wait1();
        __syncthreads();      // stage s ready; all compute on s-1 done
        if (s + 2 < nslab) issue_stage(s + 2, (s + 2) % 3);
        cp_commit();          // empty group in tail keeps accounting aligned

        const uint32_t* Aw =
            reinterpret_cast<const uint32_t*>(smh + (s % 3) * STAGEH);
        const uint32_t* Bw = Aw + ATILEH / 2;

        #pragma unroll
        for (int ks = 0; ks < 2; ks++) {     // two m16n8k16 steps
            const int pb = ks * 8;
            unsigned af[4][4];
            #pragma unroll
            for (int mt = 0; mt < 4; mt++) {
                int rb = wm * 64 + mt * 16;
                af[mt][0] = Aw[(rb + g) * 20 + pb + t4];
                af[mt][1] = Aw[(rb + g + 8) * 20 + pb + t4];
                af[mt][2] = Aw[(rb + g) * 20 + pb + t4 + 4];
                af[mt][3] = Aw[(rb + g + 8) * 20 + pb + t4 + 4];
            }
            #pragma unroll
            for (int nt = 0; nt < 8; nt++) {
                int nb = wn * 64 + nt * 8;
                unsigned bf[2];
                bf[0] = Bw[(nb + g) * 20 + pb + t4];
                bf[1] = Bw[(nb + g) * 20 + pb + t4 + 4];
                #pragma unroll
                for (int mt = 0; mt < 4; mt++)
                    mma_f16(acc[mt][nt], af[mt], bf);
            }
        }
    }

    // ---- epilogues ----
    const float sc = 0.044194173824159216f;  // 1/sqrt(512)

    #pragma unroll
    for (int mt = 0; mt < 4; mt++) {
        const int r = m0 + wm * 64 + mt * 16 + g;    // and r+8
        float inv0 = 1.f, inv1 = 1.f;
        if (DIV_EPI) {
            inv0 = __frcp_rn(Lsum[r]);
            inv1 = __frcp_rn(Lsum[r + 8]);
        }
        float sum0 = 0.f, sum1 = 0.f;
        #pragma unroll
        for (int nt = 0; nt < 8; nt++) {
            const int c = n0 + wn * 64 + nt * 8 + 2 * t4;
            float v0 = acc[mt][nt][0], v1 = acc[mt][nt][1];
            float v2 = acc[mt][nt][2], v3 = acc[mt][nt][3];
            if (EXP_EPI) {
                v0 = __expf(v0 * sc); v1 = __expf(v1 * sc);
                v2 = __expf(v2 * sc); v3 = __expf(v3 * sc);
                sum0 += v0 + v1;
                sum1 += v2 + v3;
            }
            if (DIV_EPI) { v0 *= inv0; v1 *= inv0; v2 *= inv1; v3 *= inv1; }
            if (PROJ3) {
                float b0 = bias[c], b1 = bias[c + 1];
                v0 += b0; v1 += b1; v2 += b0; v3 += b1;
            }
            if (sizeof(CT) == 2) {
                __half* Ch = reinterpret_cast<__half*>(C);
                *reinterpret_cast<__half2*>(&Ch[(long)r * N + c]) =
                    __floats2half2_rn(v0, v1);
                *reinterpret_cast<__half2*>(&Ch[(long)(r + 8) * N + c]) =
                    __floats2half2_rn(v2, v3);
            } else {
                float* Cf = reinterpret_cast<float*>(C);
                *reinterpret_cast<float2*>(&Cf[(long)r * N + c]) =
                    make_float2(v0, v1);
                *reinterpret_cast<float2*>(&Cf[(long)(r + 8) * N + c]) =
                    make_float2(v2, v3);
            }
        }
        if (EXP_EPI) {
            sum0 += __shfl_xor_sync(0xffffffffu, sum0, 1);
            sum0 += __shfl_xor_sync(0xffffffffu, sum0, 2);
            sum1 += __shfl_xor_sync(0xffffffffu, sum1, 1);
            sum1 += __shfl_xor_sync(0xffffffffu, sum1, 2);
            if (t4 == 0) {
                atomicAdd(&Lsum[r], sum0);
                atomicAdd(&Lsum[r + 8], sum1);
            }
        }
    }
}

// ---------------------------------------------------------------------------
__global__ void cvt_x_kernel(const float* __restrict__ x,
                             __half* __restrict__ xh) {
    int i = (blockIdx.x * 256 + threadIdx.x) * 4;
    float4 v = *reinterpret_cast<const float4*>(&x[i]);
    __half2 h0 = __floats2half2_rn(v.x, v.y);
    __half2 h1 = __floats2half2_rn(v.z, v.w);
    uint2 p;
    p.x = *reinterpret_cast<uint32_t*>(&h0);
    p.y = *reinterpret_cast<uint32_t*>(&h1);
    *reinterpret_cast<uint2*>(&xh[i]) = p;
}

// fp32 [R,Cc] -> fp16 transposed [Cc,R]
__global__ __launch_bounds__(256) void transpose_f2h(
    const float* __restrict__ src, __half* __restrict__ dst, int R, int Cc)
{
    __shared__ __half t[32][33];
    int x = blockIdx.x * 32 + threadIdx.x;
    int y0 = blockIdx.y * 32 + threadIdx.y;
    #pragma unroll
    for (int i = 0; i < 32; i += 8)
        t[threadIdx.y + i][threadIdx.x] = __float2half(src[(long)(y0 + i) * Cc + x]);
    __syncthreads();
    int x2 = blockIdx.y * 32 + threadIdx.x;
    int y2 = blockIdx.x * 32 + threadIdx.y;
    #pragma unroll
    for (int i = 0; i < 32; i += 8)
        dst[(long)(y2 + i) * R + x2] = t[threadIdx.x][threadIdx.y + i];
}

// fp16 [R,Cc] -> fp16 transposed [Cc,R], batched
__global__ __launch_bounds__(256) void transpose_h2h(
    const __half* __restrict__ src, __half* __restrict__ dst,
    int R, int Cc, long sSrc, long sDst)
{
    __shared__ __half t[32][33];
    src += (long)blockIdx.z * sSrc;
    dst += (long)blockIdx.z * sDst;
    int x = blockIdx.x * 32 + threadIdx.x;
    int y0 = blockIdx.y * 32 + threadIdx.y;
    #pragma unroll
    for (int i = 0; i < 32; i += 8)
        t[threadIdx.y + i][threadIdx.x] = src[(long)(y0 + i) * Cc + x];
    __syncthreads();
    int x2 = blockIdx.y * 32 + threadIdx.x;
    int y2 = blockIdx.x * 32 + threadIdx.y;
    #pragma unroll
    for (int i = 0; i < 32; i += 8)
        dst[(long)(y2 + i) * R + x2] = t[threadIdx.x][threadIdx.y + i];
}

__global__ void zero_L_kernel(float* __restrict__ L) {
    L[blockIdx.x * 1024 + threadIdx.x] = 0.f;
}

// ---------------------------------------------------------------------------
extern "C" void kernel_launch(void* const* d_in, const int* in_sizes, int n_in,
                              void* d_out, int out_size)
{
    const float* x  = (const float*)d_in[0];
    const float* Wq = (const float*)d_in[1];
    const float* bq = (const float*)d_in[2];
    const float* Wk = (const float*)d_in[3];
    const float* bk = (const float*)d_in[4];
    const float* Wv = (const float*)d_in[5];
    const float* bv = (const float*)d_in[6];
    float* out = (float*)d_out;

    __half *xh, *WT, *Qh, *Kh, *Vh, *VTh, *Ph;
    float* L;
    cudaGetSymbolAddress((void**)&xh,  g_xh);
    cudaGetSymbolAddress((void**)&WT,  g_WT);
    cudaGetSymbolAddress((void**)&Qh,  g_Qh);
    cudaGetSymbolAddress((void**)&Kh,  g_Kh);
    cudaGetSymbolAddress((void**)&Vh,  g_Vh);
    cudaGetSymbolAddress((void**)&VTh, g_VTh);
    cudaGetSymbolAddress((void**)&Ph,  g_Ph);
    cudaGetSymbolAddress((void**)&L,   g_L);

    auto kproj = gemm_h<128, true,  false, false, __half>;
    auto kqkt  = gemm_h<128, false, true,  false, __half>;
    auto kpv   = gemm_h<64,  false, false, true,  float >;
    const int smem128 = GEMM_SMEM_MT(128);   // 61440
    const int smem64  = GEMM_SMEM_MT(64);    // 46080
    cudaFuncSetAttribute(kproj, cudaFuncAttributeMaxDynamicSharedMemorySize, smem128);
    cudaFuncSetAttribute(kqkt,  cudaFuncAttributeMaxDynamicSharedMemorySize, smem128);
    cudaFuncSetAttribute(kpv,   cudaFuncAttributeMaxDynamicSharedMemorySize, smem64);

    const long WSZ = (long)DIM * DIM;
    dim3 tb(32, 8);
    Proj3Args none{};

    // 0) conversions + zero L
    cvt_x_kernel<<<MTOT * DIM / 1024, 256>>>(x, xh);
    transpose_f2h<<<dim3(16, 16), tb>>>(Wq, WT + 0 * WSZ, DIM, DIM);
    transpose_f2h<<<dim3(16, 16), tb>>>(Wk, WT + 1 * WSZ, DIM, DIM);
    transpose_f2h<<<dim3(16, 16), tb>>>(Wv, WT + 2 * WSZ, DIM, DIM);
    zero_L_kernel<<<BATCH * SEQ / 1024, 1024>>>(L);

    // 1) merged projections: z picks Q/K/V.  M=16384 N=512 K=512
    Proj3Args pa;
    pa.B[0] = WT + 0 * WSZ; pa.B[1] = WT + 1 * WSZ; pa.B[2] = WT + 2 * WSZ;
    pa.bias[0] = bq; pa.bias[1] = bk; pa.bias[2] = bv;
    pa.C[0] = Qh; pa.C[1] = Kh; pa.C[2] = Vh;
    dim3 gp(DIM / 128, MTOT / 128, 3);
    kproj<<<gp, 128, smem128>>>(
        xh, nullptr, nullptr, (__half*)nullptr, nullptr,
        MTOT, DIM, DIM, 0, 0, 0, pa);

    // 2) V^T per batch (fp16)
    transpose_h2h<<<dim3(DIM / 32, SEQ / 32, BATCH), tb>>>(
        Vh, VTh, SEQ, DIM, (long)SEQ * DIM, (long)DIM * SEQ);

    // 3) P = exp(Q K^T * sc) fp16, row sums -> L
    dim3 gs(SEQ / 128, SEQ / 128, BATCH);
    kqkt<<<gs, 128, smem128>>>(
        Qh, Kh, nullptr, Ph, L, SEQ, SEQ, DIM,
        (long)SEQ * DIM, (long)SEQ * DIM, (long)SEQ * SEQ, none);

    // 4) out = (P @ V) / L  (NT vs V^T), float out.  MT=64: 1024 CTAs.
    dim3 go(DIM / 128, SEQ / 64, BATCH);
    kpv<<<go, 64, smem64>>>(
        Ph, VTh, nullptr, out, L, SEQ, DIM, SEQ,
        (long)SEQ * SEQ, (long)DIM * SEQ, (long)SEQ * DIM, none);
}

// round 15
// speedup vs baseline: 1.1473x; 1.1473x over previous
#include <cuda_runtime.h>
#include <cuda_fp16.h>
#include <cstdint>

#define SEQ   4096
#define DIM   512
#define BATCH 4
#define MTOT  (BATCH*SEQ)
#define KC    4                      // PV split-K chunks

// Device-global scratch (allocation-free).
__device__ __align__(16) __half g_xh [(size_t)MTOT * DIM];
__device__ __align__(16) __half g_WT [3][(size_t)DIM * DIM];   // W^T fp16
__device__ __align__(16) __half g_Qh [(size_t)MTOT * DIM];
__device__ __align__(16) __half g_Kh [(size_t)MTOT * DIM];
__device__ __align__(16) __half g_Vh [(size_t)MTOT * DIM];
__device__ __align__(16) __half g_VTh[(size_t)BATCH * DIM * SEQ]; // V^T fp16
__device__ __align__(16) __half g_Ph [(size_t)BATCH * SEQ * SEQ]; // probs fp16
__device__ __align__(16) float  g_O4 [(size_t)BATCH * KC * SEQ * DIM]; // PV partials
__device__ float g_L[(size_t)BATCH * SEQ];                        // denominators

struct Proj3Args {
    const __half* B[3];
    const float*  bias[3];
    __half*       C[3];
};

// ---------------------------------------------------------------------------
__device__ __forceinline__ void mma_f16(float* d, const unsigned* a,
                                        const unsigned* b) {
    asm volatile(
        "mma.sync.aligned.m16n8k16.row.col.f32.f16.f16.f32 "
        "{%0,%1,%2,%3}, {%4,%5,%6,%7}, {%8,%9}, {%0,%1,%2,%3};"
        : "+f"(d[0]), "+f"(d[1]), "+f"(d[2]), "+f"(d[3])
        : "r"(a[0]), "r"(a[1]), "r"(a[2]), "r"(a[3]),
          "r"(b[0]), "r"(b[1]));
}
__device__ __forceinline__ uint32_t smem_u32(const void* p) {
    uint32_t a;
    asm("{ .reg .u64 t; cvta.to.shared.u64 t, %1; cvt.u32.u64 %0, t; }"
        : "=r"(a) : "l"(p));
    return a;
}
__device__ __forceinline__ void cp16(uint32_t dst, const void* src) {
    asm volatile("cp.async.ca.shared.global [%0], [%1], 16;"
                 :: "r"(dst), "l"(src));
}
__device__ __forceinline__ void cp_commit() {
    asm volatile("cp.async.commit_group;");
}
__device__ __forceinline__ void cp_wait1() {
    asm volatile("cp.async.wait_group 1;");
}

// Stage geometry (halfs): per stage [ A:128*40 | B:128*40 ], 3 stages.
#define TILEH   (128 * 40)
#define STAGEH  (2 * TILEH)
#define GEMM_SMEM (3 * STAGEH * 2)   // bytes = 61440

// ---------------------------------------------------------------------------
// fp16 NT GEMM:  C = A @ B^T.  A:[M,K] halfs k-major, B:[N,K] halfs k-major.
// CTA tile 128x128, 128 threads, 3 CTAs/SM, k-slab 32, 3-stage cp.async.
// Warp grid 2x2; warp tile 64x64 = 4 m-tiles x 8 n-tiles of m16n8k16.
// smem rows padded to 40 halfs (20 words): frag banks (g*20+t4)%32 distinct.
// Modes: PROJ3 (z selects W/bias/out; +bias, half out),
//        EXP (exp*sc + row-sum atomics, half out),
//        SPLITK (z = b*KC+kc; K-chunk of 1024; raw float partials out).
// ---------------------------------------------------------------------------
template<bool PROJ3, bool EXP_EPI, bool SPLITK, typename CT>
__global__ __launch_bounds__(128, 3) void gemm_h(
    const __half* __restrict__ A, const __half* __restrict__ B,
    const float* __restrict__ bias, CT* __restrict__ C,
    float* __restrict__ Lsum,
    int M, int N, int K, long sA, long sB, long sC, Proj3Args p3)
{
    if (PROJ3) {
        B    = p3.B[blockIdx.z];
        bias = p3.bias[blockIdx.z];
        C    = (CT*)p3.C[blockIdx.z];
    } else if (SPLITK) {
        const int b = blockIdx.z >> 2, kc = blockIdx.z & 3;
        A += (long)b * sA + (long)kc * (SEQ / KC);
        B += (long)b * sB + (long)kc * (SEQ / KC);
        C += (long)blockIdx.z * ((long)SEQ * DIM);
    } else {
        A += (long)blockIdx.z * sA;
        B += (long)blockIdx.z * sB;
        C += (long)blockIdx.z * sC;
        if (EXP_EPI) Lsum += (long)blockIdx.z * SEQ;
    }

    extern __shared__ __align__(16) __half smh[];

    const int tid  = threadIdx.x;
    const int lane = tid & 31, w = tid >> 5;
    const int g    = lane >> 2, t4 = lane & 3;
    const int wm   = w & 1, wn = w >> 1;
    const int m0   = blockIdx.y * 128, n0 = blockIdx.x * 128;

    const uint32_t sb = smem_u32(smh);
    const long Klong = K;   // row stride of A/B in halfs is the FULL K
    const long Arow  = SPLITK ? (long)SEQ : Klong;
    const long Brow  = SPLITK ? (long)SEQ : Klong;

    auto issue_stage = [&](int s, int st) {
        const int k0 = s << 5;
        const uint32_t ab = sb + st * (STAGEH * 2);
        #pragma unroll
        for (int i = 0; i < 4; i++) {       // A: 512 16B chunks, 4/thread
            int c = tid + i * 128;
            int row = c >> 2, ko = (c & 3) * 8;
            cp16(ab + row * 80 + ko * 2,
                 &A[(long)(m0 + row) * Arow + k0 + ko]);
        }
        const uint32_t bb = ab + TILEH * 2;
        #pragma unroll
        for (int i = 0; i < 4; i++) {       // B
            int c = tid + i * 128;
            int row = c >> 2, ko = (c & 3) * 8;
            cp16(bb + row * 80 + ko * 2,
                 &B[(long)(n0 + row) * Brow + k0 + ko]);
        }
    };

    float acc[4][8][4];
    #pragma unroll
    for (int mt = 0; mt < 4; mt++)
        #pragma unroll
        for (int nt = 0; nt < 8; nt++)
            #pragma unroll
            for (int i = 0; i < 4; i++) acc[mt][nt][i] = 0.f;

    const int nslab = K >> 5;
    issue_stage(0, 0); cp_commit();
    issue_stage(1, 1); cp_commit();

    for (int s = 0; s < nslab; s++) {
        cp_wait1();
        __syncthreads();      // stage s ready; all compute on s-1 done
        if (s + 2 < nslab) issue_stage(s + 2, (s + 2) % 3);
        cp_commit();          // empty group in tail keeps accounting aligned

        const uint32_t* Aw =
            reinterpret_cast<const uint32_t*>(smh + (s % 3) * STAGEH);
        const uint32_t* Bw = Aw + TILEH / 2;

        #pragma unroll
        for (int ks = 0; ks < 2; ks++) {     // two m16n8k16 steps
            const int pb = ks * 8;
            unsigned af[4][4];
            #pragma unroll
            for (int mt = 0; mt < 4; mt++) {
                int rb = wm * 64 + mt * 16;
                af[mt][0] = Aw[(rb + g) * 20 + pb + t4];
                af[mt][1] = Aw[(rb + g + 8) * 20 + pb + t4];
                af[mt][2] = Aw[(rb + g) * 20 + pb + t4 + 4];
                af[mt][3] = Aw[(rb + g + 8) * 20 + pb + t4 + 4];
            }
            #pragma unroll
            for (int nt = 0; nt < 8; nt++) {
                int nb = wn * 64 + nt * 8;
                unsigned bf[2];
                bf[0] = Bw[(nb + g) * 20 + pb + t4];
                bf[1] = Bw[(nb + g) * 20 + pb + t4 + 4];
                #pragma unroll
                for (int mt = 0; mt < 4; mt++)
                    mma_f16(acc[mt][nt], af[mt], bf);
            }
        }
    }

    // ---- epilogues ----
    const float sc = 0.044194173824159216f;  // 1/sqrt(512)

    #pragma unroll
    for (int mt = 0; mt < 4; mt++) {
        const int r = m0 + wm * 64 + mt * 16 + g;    // and r+8
        float sum0 = 0.f, sum1 = 0.f;
        #pragma unroll
        for (int nt = 0; nt < 8; nt++) {
            const int c = n0 + wn * 64 + nt * 8 + 2 * t4;
            float v0 = acc[mt][nt][0], v1 = acc[mt][nt][1];
            float v2 = acc[mt][nt][2], v3 = acc[mt][nt][3];
            if (EXP_EPI) {
                v0 = __expf(v0 * sc); v1 = __expf(v1 * sc);
                v2 = __expf(v2 * sc); v3 = __expf(v3 * sc);
                sum0 += v0 + v1;
                sum1 += v2 + v3;
            }
            if (PROJ3) {
                float b0 = bias[c], b1 = bias[c + 1];
                v0 += b0; v1 += b1; v2 += b0; v3 += b1;
            }
            if (sizeof(CT) == 2) {
                __half* Ch = reinterpret_cast<__half*>(C);
                *reinterpret_cast<__half2*>(&Ch[(long)r * N + c]) =
                    __floats2half2_rn(v0, v1);
                *reinterpret_cast<__half2*>(&Ch[(long)(r + 8) * N + c]) =
                    __floats2half2_rn(v2, v3);
            } else {
                float* Cf = reinterpret_cast<float*>(C);
                *reinterpret_cast<float2*>(&Cf[(long)r * N + c]) =
                    make_float2(v0, v1);
                *reinterpret_cast<float2*>(&Cf[(long)(r + 8) * N + c]) =
                    make_float2(v2, v3);
            }
        }
        if (EXP_EPI) {
            sum0 += __shfl_xor_sync(0xffffffffu, sum0, 1);
            sum0 += __shfl_xor_sync(0xffffffffu, sum0, 2);
            sum1 += __shfl_xor_sync(0xffffffffu, sum1, 1);
            sum1 += __shfl_xor_sync(0xffffffffu, sum1, 2);
            if (t4 == 0) {
                atomicAdd(&Lsum[r], sum0);
                atomicAdd(&Lsum[r + 8], sum1);
            }
        }
    }
}

// ---------------------------------------------------------------------------
// Reduce PV partials: out[i] = (sum_kc part[...]) / L[row].
// i indexes the full BATCH*SEQ*DIM output; 4 floats per thread.
__global__ __launch_bounds__(256) void reduce_pv(
    const float* __restrict__ part, const float* __restrict__ L,
    float* __restrict__ out)
{
    const long SD = (long)SEQ * DIM;
    long i = ((long)blockIdx.x * 256 + threadIdx.x) * 4;
    long b = i / SD;
    long base = i + b * (KC - 1) * SD;
    float4 a0 = *reinterpret_cast<const float4*>(&part[base]);
    #pragma unroll
    for (int kc = 1; kc < KC; kc++) {
        float4 p = *reinterpret_cast<const float4*>(&part[base + (long)kc * SD]);
        a0.x += p.x; a0.y += p.y; a0.z += p.z; a0.w += p.w;
    }
    float inv = __frcp_rn(L[i >> 9]);    // global row = i / DIM
    a0.x *= inv; a0.y *= inv; a0.z *= inv; a0.w *= inv;
    *reinterpret_cast<float4*>(&out[i]) = a0;
}

// ---------------------------------------------------------------------------
__global__ void cvt_x_kernel(const float* __restrict__ x,
                             __half* __restrict__ xh) {
    int i = (blockIdx.x * 256 + threadIdx.x) * 4;
    float4 v = *reinterpret_cast<const float4*>(&x[i]);
    __half2 h0 = __floats2half2_rn(v.x, v.y);
    __half2 h1 = __floats2half2_rn(v.z, v.w);
    uint2 p;
    p.x = *reinterpret_cast<uint32_t*>(&h0);
    p.y = *reinterpret_cast<uint32_t*>(&h1);
    *reinterpret_cast<uint2*>(&xh[i]) = p;
}

// fp32 [R,Cc] -> fp16 transposed [Cc,R]
__global__ __launch_bounds__(256) void transpose_f2h(
    const float* __restrict__ src, __half* __restrict__ dst, int R, int Cc)
{
    __shared__ __half t[32][33];
    int x = blockIdx.x * 32 + threadIdx.x;
    int y0 = blockIdx.y * 32 + threadIdx.y;
    #pragma unroll
    for (int i = 0; i < 32; i += 8)
        t[threadIdx.y + i][threadIdx.x] = __float2half(src[(long)(y0 + i) * Cc + x]);
    __syncthreads();
    int x2 = blockIdx.y * 32 + threadIdx.x;
    int y2 = blockIdx.x * 32 + threadIdx.y;
    #pragma unroll
    for (int i = 0; i < 32; i += 8)
        dst[(long)(y2 + i) * R + x2] = t[threadIdx.x][threadIdx.y + i];
}

// fp16 [R,Cc] -> fp16 transposed [Cc,R], batched
__global__ __launch_bounds__(256) void transpose_h2h(
    const __half* __restrict__ src, __half* __restrict__ dst,
    int R, int Cc, long sSrc, long sDst)
{
    __shared__ __half t[32][33];
    src += (long)blockIdx.z * sSrc;
    dst += (long)blockIdx.z * sDst;
    int x = blockIdx.x * 32 + threadIdx.x;
    int y0 = blockIdx.y * 32 + threadIdx.y;
    #pragma unroll
    for (int i = 0; i < 32; i += 8)
        t[threadIdx.y + i][threadIdx.x] = src[(long)(y0 + i) * Cc + x];
    __syncthreads();
    int x2 = blockIdx.y * 32 + threadIdx.x;
    int y2 = blockIdx.x * 32 + threadIdx.y;
    #pragma unroll
    for (int i = 0; i < 32; i += 8)
        dst[(long)(y2 + i) * R + x2] = t[threadIdx.x][threadIdx.y + i];
}

__global__ void zero_L_kernel(float* __restrict__ L) {
    L[blockIdx.x * 1024 + threadIdx.x] = 0.f;
}

// ---------------------------------------------------------------------------
extern "C" void kernel_launch(void* const* d_in, const int* in_sizes, int n_in,
                              void* d_out, int out_size)
{
    const float* x  = (const float*)d_in[0];
    const float* Wq = (const float*)d_in[1];
    const float* bq = (const float*)d_in[2];
    const float* Wk = (const float*)d_in[3];
    const float* bk = (const float*)d_in[4];
    const float* Wv = (const float*)d_in[5];
    const float* bv = (const float*)d_in[6];
    float* out = (float*)d_out;

    __half *xh, *WT, *Qh, *Kh, *Vh, *VTh, *Ph;
    float *L, *O4;
    cudaGetSymbolAddress((void**)&xh,  g_xh);
    cudaGetSymbolAddress((void**)&WT,  g_WT);
    cudaGetSymbolAddress((void**)&Qh,  g_Qh);
    cudaGetSymbolAddress((void**)&Kh,  g_Kh);
    cudaGetSymbolAddress((void**)&Vh,  g_Vh);
    cudaGetSymbolAddress((void**)&VTh, g_VTh);
    cudaGetSymbolAddress((void**)&Ph,  g_Ph);
    cudaGetSymbolAddress((void**)&O4,  g_O4);
    cudaGetSymbolAddress((void**)&L,   g_L);

    auto kproj = gemm_h<true,  false, false, __half>;
    auto kqkt  = gemm_h<false, true,  false, __half>;
    auto kpv   = gemm_h<false, false, true,  float >;
    cudaFuncSetAttribute(kproj, cudaFuncAttributeMaxDynamicSharedMemorySize, GEMM_SMEM);
    cudaFuncSetAttribute(kqkt,  cudaFuncAttributeMaxDynamicSharedMemorySize, GEMM_SMEM);
    cudaFuncSetAttribute(kpv,   cudaFuncAttributeMaxDynamicSharedMemorySize, GEMM_SMEM);

    const long WSZ = (long)DIM * DIM;
    dim3 tb(32, 8);
    Proj3Args none{};

    // 0) conversions + zero L
    cvt_x_kernel<<<MTOT * DIM / 1024, 256>>>(x, xh);
    transpose_f2h<<<dim3(16, 16), tb>>>(Wq, WT + 0 * WSZ, DIM, DIM);
    transpose_f2h<<<dim3(16, 16), tb>>>(Wk, WT + 1 * WSZ, DIM, DIM);
    transpose_f2h<<<dim3(16, 16), tb>>>(Wv, WT + 2 * WSZ, DIM, DIM);
    zero_L_kernel<<<BATCH * SEQ / 1024, 1024>>>(L);

    // 1) merged projections: z picks Q/K/V.  M=16384 N=512 K=512
    Proj3Args pa;
    pa.B[0] = WT + 0 * WSZ; pa.B[1] = WT + 1 * WSZ; pa.B[2] = WT + 2 * WSZ;
    pa.bias[0] = bq; pa.bias[1] = bk; pa.bias[2] = bv;
    pa.C[0] = Qh; pa.C[1] = Kh; pa.C[2] = Vh;
    dim3 gp(DIM / 128, MTOT / 128, 3);
    kproj<<<gp, 128, GEMM_SMEM>>>(
        xh, nullptr, nullptr, (__half*)nullptr, nullptr,
        MTOT, DIM, DIM, 0, 0, 0, pa);

    // 2) V^T per batch (fp16)
    transpose_h2h<<<dim3(DIM / 32, SEQ / 32, BATCH), tb>>>(
        Vh, VTh, SEQ, DIM, (long)SEQ * DIM, (long)DIM * SEQ);

    // 3) P = exp(Q K^T * sc) fp16, row sums -> L
    dim3 gs(SEQ / 128, SEQ / 128, BATCH);
    kqkt<<<gs, 128, GEMM_SMEM>>>(
        Qh, Kh, nullptr, Ph, L, SEQ, SEQ, DIM,
        (long)SEQ * DIM, (long)SEQ * DIM, (long)SEQ * SEQ, none);

    // 4) PV split-K: z = b*KC+kc, K-chunk 1024, partials -> O4
    dim3 go(DIM / 128, SEQ / 128, BATCH * KC);
    kpv<<<go, 128, GEMM_SMEM>>>(
        Ph, VTh, nullptr, O4, nullptr, SEQ, DIM, SEQ / KC,
        (long)SEQ * SEQ, (long)DIM * SEQ, 0, none);

    // 5) reduce partials + divide by L
    reduce_pv<<<(int)(((long)MTOT * DIM / 4) / 256), 256>>>(O4, L, out);
}